// round 1
// baseline (speedup 1.0000x reference)
#include <cuda_runtime.h>
#include <math.h>
#include <float.h>

// Problem constants
#define SEQ    4096
#define HID    2048
#define NHEAD  16
#define HDIM   128
#define NSTART 410            // ceil(0.1 * 4096)
#define NKEY   1434           // 410 + 1024 allowed key positions
#define KOFF   2662           // 3072 - 410 : offset for "recent" keys

// Scratch (device globals: no runtime allocation allowed)
__device__ float  g_Q[SEQ * HID];
__device__ float  g_K[NKEY * HID];
__device__ float  g_V[NKEY * HID];
__device__ float  g_CTX[SEQ * HID];
__device__ float2 g_rope[SEQ * 64];   // (sin, cos) per (pos, pair)

// ---------------------------------------------------------------------------
// RoPE table: computed in double so we're at least as accurate as the fp32 ref
// ---------------------------------------------------------------------------
__global__ void rope_table_kernel() {
    int idx = blockIdx.x * blockDim.x + threadIdx.x;
    if (idx >= SEQ * 64) return;
    int pos = idx >> 6;
    int d   = idx & 63;
    double theta = pow(10000.0, -(double)(2 * d) / 128.0);
    double ang   = (double)pos * theta;
    g_rope[idx] = make_float2((float)sin(ang), (float)cos(ang));
}

// ---------------------------------------------------------------------------
// SGEMM (TN): C[M,N] = A[M,K] * B[N,K]^T + bias, optional row-gather on A
// (to compute K/V only for unmasked key positions) and fused interleaved RoPE.
// 128x128 tile, BK=8, 256 threads, 8x8 micro-tile per thread.
// ---------------------------------------------------------------------------
template<int GATHER, int ROPE>
__global__ void __launch_bounds__(256, 2)
sgemm_tn(const float* __restrict__ A, const float* __restrict__ B,
         const float* __restrict__ bias, float* __restrict__ C,
         int M, int N, int K)
{
    __shared__ float As[8][128];
    __shared__ float Bs[8][128];

    const int tid = threadIdx.x;
    const int tr  = tid >> 4;        // 0..15 : row group
    const int tc  = tid & 15;        // 0..15 : col group
    const int lr  = tid >> 1;        // 0..127: load row
    const int lk  = (tid & 1) << 2;  // 0 or 4: load k offset

    const int arow = blockIdx.y * 128 + lr;
    int apos = arow;
    if (GATHER) apos = (arow < NSTART) ? arow : (arow + KOFF);
    const bool aval = (arow < M);
    const float* Aptr = A + (size_t)apos * K + lk;
    const float* Bptr = B + (size_t)(blockIdx.x * 128 + lr) * K + lk;

    float acc[8][8];
#pragma unroll
    for (int i = 0; i < 8; i++)
#pragma unroll
        for (int j = 0; j < 8; j++) acc[i][j] = 0.f;

    for (int k0 = 0; k0 < K; k0 += 8) {
        float4 av = make_float4(0.f, 0.f, 0.f, 0.f);
        if (aval) av = *(const float4*)(Aptr + k0);
        float4 bv = *(const float4*)(Bptr + k0);
        As[lk + 0][lr] = av.x; As[lk + 1][lr] = av.y;
        As[lk + 2][lr] = av.z; As[lk + 3][lr] = av.w;
        Bs[lk + 0][lr] = bv.x; Bs[lk + 1][lr] = bv.y;
        Bs[lk + 2][lr] = bv.z; Bs[lk + 3][lr] = bv.w;
        __syncthreads();

        float a[8], b[8];
#pragma unroll
        for (int kk = 0; kk < 8; kk++) {
            *(float4*)&a[0] = *(const float4*)&As[kk][tr * 8];
            *(float4*)&a[4] = *(const float4*)&As[kk][tr * 8 + 4];
            *(float4*)&b[0] = *(const float4*)&Bs[kk][tc * 4];
            *(float4*)&b[4] = *(const float4*)&Bs[kk][64 + tc * 4];
#pragma unroll
            for (int i = 0; i < 8; i++)
#pragma unroll
                for (int j = 0; j < 8; j++)
                    acc[i][j] = fmaf(a[i], b[j], acc[i][j]);
        }
        __syncthreads();
    }

#pragma unroll
    for (int i = 0; i < 8; i++) {
        const int row = blockIdx.y * 128 + tr * 8 + i;
        if (row >= M) break;
        int pos = row;
        if (GATHER) pos = (row < NSTART) ? row : (row + KOFF);
#pragma unroll
        for (int g = 0; g < 2; g++) {
            const int col = blockIdx.x * 128 + g * 64 + tc * 4;
            float4 v;
            v.x = acc[i][g * 4 + 0] + bias[col + 0];
            v.y = acc[i][g * 4 + 1] + bias[col + 1];
            v.z = acc[i][g * 4 + 2] + bias[col + 2];
            v.w = acc[i][g * 4 + 3] + bias[col + 3];
            if (ROPE) {
                // interleaved rotation on adjacent pairs; exactly preserves q.k
                const int d0 = (col & 127) >> 1;
                float2 sc0 = g_rope[pos * 64 + d0];
                float2 sc1 = g_rope[pos * 64 + d0 + 1];
                float x1 = v.x, x2 = v.y;
                v.x = x1 * sc0.y - x2 * sc0.x;
                v.y = x1 * sc0.x + x2 * sc0.y;
                x1 = v.z; x2 = v.w;
                v.z = x1 * sc1.y - x2 * sc1.x;
                v.w = x1 * sc1.x + x2 * sc1.y;
            }
            *(float4*)(C + (size_t)row * N + col) = v;
        }
    }
}

// ---------------------------------------------------------------------------
// Flash-style attention over the fixed 1434-key set.
// Grid: (SEQ/64 q-blocks, 16 heads). 256 threads.
// smem: Qs[64][132], Ks[64][132], Vs[64][128], Ps[64][68] (P transposed)
// ---------------------------------------------------------------------------
#define QS_STR 132
#define KS_STR 132
#define VS_STR 128
#define PS_STR 68
#define ATTN_SMEM ((64*QS_STR + 64*KS_STR + 64*VS_STR + 64*PS_STR) * 4)

__global__ void __launch_bounds__(256, 1)
attn_kernel()
{
    extern __shared__ float smf[];
    float* Qs = smf;
    float* Ks = Qs + 64 * QS_STR;
    float* Vs = Ks + 64 * KS_STR;
    float* Ps = Vs + 64 * VS_STR;   // Ps[j][r] transposed

    const int qb  = blockIdx.x;
    const int h   = blockIdx.y;
    const int tid = threadIdx.x;
    const int ty  = tid >> 4;       // 0..15
    const int tx  = tid & 15;       // 0..15

    // Load Q tile [64 x 128]
    {
        const int row = tid >> 2;
        const int c0  = (tid & 3) * 32;
        const float* src = g_Q + (size_t)(qb * 64 + row) * HID + h * HDIM + c0;
        float* dst = Qs + row * QS_STR + c0;
#pragma unroll
        for (int i = 0; i < 8; i++)
            *(float4*)(dst + 4 * i) = *(const float4*)(src + 4 * i);
    }

    float m[4], l[4], o[4][8];
#pragma unroll
    for (int i = 0; i < 4; i++) {
        m[i] = -INFINITY; l[i] = 0.f;
#pragma unroll
        for (int c = 0; c < 8; c++) o[i][c] = 0.f;
    }

    const float scale = 0.088388347648318447f;  // 1/sqrt(128)
    const int ntiles = (NKEY + 63) >> 6;        // 23

    for (int kt = 0; kt < ntiles; kt++) {
        __syncthreads();   // protect Ks/Vs/Ps (and Qs on first iter)
        {
            const int row = tid >> 2;
            const int c0  = (tid & 3) * 32;
            const int kr  = kt * 64 + row;
            float* kd = Ks + row * KS_STR + c0;
            float* vd = Vs + row * VS_STR + c0;
            if (kr < NKEY) {
                const float* ks = g_K + (size_t)kr * HID + h * HDIM + c0;
                const float* vs = g_V + (size_t)kr * HID + h * HDIM + c0;
#pragma unroll
                for (int i = 0; i < 8; i++) {
                    *(float4*)(kd + 4 * i) = *(const float4*)(ks + 4 * i);
                    *(float4*)(vd + 4 * i) = *(const float4*)(vs + 4 * i);
                }
            } else {
                float4 z = make_float4(0.f, 0.f, 0.f, 0.f);
#pragma unroll
                for (int i = 0; i < 8; i++) {
                    *(float4*)(kd + 4 * i) = z;
                    *(float4*)(vd + 4 * i) = z;
                }
            }
        }
        __syncthreads();

        // S = Q K^T : thread owns rows 4ty+i, cols 4tx+j
        float s[4][4];
#pragma unroll
        for (int i = 0; i < 4; i++)
#pragma unroll
            for (int j = 0; j < 4; j++) s[i][j] = 0.f;

        for (int k4 = 0; k4 < 32; k4++) {
            float4 qv[4], kv[4];
#pragma unroll
            for (int i = 0; i < 4; i++)
                qv[i] = *(const float4*)&Qs[(ty * 4 + i) * QS_STR + k4 * 4];
#pragma unroll
            for (int j = 0; j < 4; j++)
                kv[j] = *(const float4*)&Ks[(tx * 4 + j) * KS_STR + k4 * 4];
#pragma unroll
            for (int i = 0; i < 4; i++)
#pragma unroll
                for (int j = 0; j < 4; j++) {
                    s[i][j] = fmaf(qv[i].x, kv[j].x, s[i][j]);
                    s[i][j] = fmaf(qv[i].y, kv[j].y, s[i][j]);
                    s[i][j] = fmaf(qv[i].z, kv[j].z, s[i][j]);
                    s[i][j] = fmaf(qv[i].w, kv[j].w, s[i][j]);
                }
        }

#pragma unroll
        for (int i = 0; i < 4; i++)
#pragma unroll
            for (int j = 0; j < 4; j++) {
                const int kr = kt * 64 + tx * 4 + j;
                s[i][j] = (kr < NKEY) ? s[i][j] * scale : -INFINITY;
            }

        // online softmax per row (reduce over tx = lane bits 0..3)
#pragma unroll
        for (int i = 0; i < 4; i++) {
            float tmax = fmaxf(fmaxf(s[i][0], s[i][1]), fmaxf(s[i][2], s[i][3]));
#pragma unroll
            for (int w = 8; w >= 1; w >>= 1)
                tmax = fmaxf(tmax, __shfl_xor_sync(0xffffffffu, tmax, w));
            const float mn   = fmaxf(m[i], tmax);
            const float corr = expf(m[i] - mn);
            float p[4], psum = 0.f;
#pragma unroll
            for (int j = 0; j < 4; j++) {
                p[j] = expf(s[i][j] - mn);
                psum += p[j];
            }
#pragma unroll
            for (int w = 8; w >= 1; w >>= 1)
                psum += __shfl_xor_sync(0xffffffffu, psum, w);
            l[i] = l[i] * corr + psum;
            m[i] = mn;
#pragma unroll
            for (int c = 0; c < 8; c++) o[i][c] *= corr;
#pragma unroll
            for (int j = 0; j < 4; j++)
                Ps[(tx * 4 + j) * PS_STR + ty * 4 + i] = p[j];
        }
        __syncthreads();

        // O += P V : thread owns rows 4ty+i, cols 8tx..8tx+7
        for (int j = 0; j < 64; j++) {
            float4 pv = *(const float4*)&Ps[j * PS_STR + ty * 4];
            float4 v0 = *(const float4*)&Vs[j * VS_STR + tx * 8];
            float4 v1 = *(const float4*)&Vs[j * VS_STR + tx * 8 + 4];
            float pa[4] = {pv.x, pv.y, pv.z, pv.w};
#pragma unroll
            for (int i = 0; i < 4; i++) {
                o[i][0] = fmaf(pa[i], v0.x, o[i][0]);
                o[i][1] = fmaf(pa[i], v0.y, o[i][1]);
                o[i][2] = fmaf(pa[i], v0.z, o[i][2]);
                o[i][3] = fmaf(pa[i], v0.w, o[i][3]);
                o[i][4] = fmaf(pa[i], v1.x, o[i][4]);
                o[i][5] = fmaf(pa[i], v1.y, o[i][5]);
                o[i][6] = fmaf(pa[i], v1.z, o[i][6]);
                o[i][7] = fmaf(pa[i], v1.w, o[i][7]);
            }
        }
    }

    // normalize + write ctx in [s, h*128+d] layout (so O-proj is standard GEMM)
#pragma unroll
    for (int i = 0; i < 4; i++) {
        const float inv = 1.f / l[i];
        float4 r0, r1;
        r0.x = o[i][0] * inv; r0.y = o[i][1] * inv;
        r0.z = o[i][2] * inv; r0.w = o[i][3] * inv;
        r1.x = o[i][4] * inv; r1.y = o[i][5] * inv;
        r1.z = o[i][6] * inv; r1.w = o[i][7] * inv;
        float* dst = g_CTX + (size_t)(qb * 64 + ty * 4 + i) * HID + h * HDIM + tx * 8;
        *(float4*)dst       = r0;
        *(float4*)(dst + 4) = r1;
    }
}

// ---------------------------------------------------------------------------
extern "C" void kernel_launch(void* const* d_in, const int* in_sizes, int n_in,
                              void* d_out, int out_size)
{
    const float* X  = (const float*)d_in[0];
    const float* Wq = (const float*)d_in[1];
    const float* bq = (const float*)d_in[2];
    const float* Wk = (const float*)d_in[3];
    const float* bk = (const float*)d_in[4];
    const float* Wv = (const float*)d_in[5];
    const float* bv = (const float*)d_in[6];
    const float* Wo = (const float*)d_in[7];
    const float* bo = (const float*)d_in[8];
    float* out = (float*)d_out;

    float *Qp, *Kp, *Vp, *Cp;
    cudaGetSymbolAddress((void**)&Qp, g_Q);
    cudaGetSymbolAddress((void**)&Kp, g_K);
    cudaGetSymbolAddress((void**)&Vp, g_V);
    cudaGetSymbolAddress((void**)&Cp, g_CTX);

    rope_table_kernel<<<(SEQ * 64 + 255) / 256, 256>>>();

    dim3 blk(256);
    // Q = X Wq^T + bq, rope
    sgemm_tn<0, 1><<<dim3(HID / 128, SEQ / 128), blk>>>(X, Wq, bq, Qp, SEQ, HID, HID);
    // K,V only for the 1434 unmasked key positions (gathered rows)
    sgemm_tn<1, 1><<<dim3(HID / 128, (NKEY + 127) / 128), blk>>>(X, Wk, bk, Kp, NKEY, HID, HID);
    sgemm_tn<1, 0><<<dim3(HID / 128, (NKEY + 127) / 128), blk>>>(X, Wv, bv, Vp, NKEY, HID, HID);

    cudaFuncSetAttribute(attn_kernel, cudaFuncAttributeMaxDynamicSharedMemorySize, ATTN_SMEM);
    attn_kernel<<<dim3(SEQ / 64, NHEAD), blk, ATTN_SMEM>>>();

    // out = CTX Wo^T + bo
    sgemm_tn<0, 0><<<dim3(HID / 128, SEQ / 128), blk>>>(Cp, Wo, bo, out, SEQ, HID, HID);
}

// round 3
// speedup vs baseline: 1.7758x; 1.7758x over previous
#include <cuda_runtime.h>
#include <cuda_bf16.h>
#include <math.h>
#include <stdint.h>

// ---------------------------------------------------------------------------
// Problem constants
// ---------------------------------------------------------------------------
#define SEQ    4096
#define HID    2048
#define NHEAD  16
#define HDIM   128
#define NSTART 410            // ceil(0.1 * 4096)
#define NKEY   1434           // 410 + 1024 allowed key positions
#define KOFF   2662           // 3072 - 410
#define MKV    1536           // NKEY padded to multiple of 128

// ---------------------------------------------------------------------------
// Device-global scratch (no runtime allocation allowed)
// ---------------------------------------------------------------------------
__device__ float  g_Q[SEQ * HID];
__device__ float  g_K[MKV * HID];
__device__ float  g_V[MKV * HID];
__device__ float  g_CTX[SEQ * HID];
__device__ float2 g_rope[SEQ * 64];

__device__ __nv_bfloat16 g_Xhi[SEQ * HID],  g_Xlo[SEQ * HID];
__device__ __nv_bfloat16 g_Xghi[MKV * HID], g_Xglo[MKV * HID];
__device__ __nv_bfloat16 g_Wqhi[HID * HID], g_Wqlo[HID * HID];
__device__ __nv_bfloat16 g_Wkhi[HID * HID], g_Wklo[HID * HID];
__device__ __nv_bfloat16 g_Wvhi[HID * HID], g_Wvlo[HID * HID];
__device__ __nv_bfloat16 g_Wohi[HID * HID], g_Wolo[HID * HID];
__device__ __nv_bfloat16 g_Chi[SEQ * HID],  g_Clo[SEQ * HID];

// ---------------------------------------------------------------------------
// Helpers
// ---------------------------------------------------------------------------
__device__ __forceinline__ uint32_t smem_u32(const void* p) {
    uint32_t a;
    asm("{ .reg .u64 t; cvta.to.shared.u64 t, %1; cvt.u32.u64 %0, t; }" : "=r"(a) : "l"(p));
    return a;
}

#define CP_ASYNC16(saddr, gaddr) \
    asm volatile("cp.async.cg.shared.global [%0], [%1], 16;" \
                 :: "r"(saddr), "l"(gaddr))
#define CP_COMMIT() asm volatile("cp.async.commit_group;" ::: "memory")
#define CP_WAIT(n)  asm volatile("cp.async.wait_group %0;" :: "n"(n) : "memory")

#define LDMATRIX_X4(r0, r1, r2, r3, addr) \
    asm volatile("ldmatrix.sync.aligned.m8n8.x4.shared.b16 {%0,%1,%2,%3}, [%4];" \
                 : "=r"(r0), "=r"(r1), "=r"(r2), "=r"(r3) : "r"(addr))

#define MMA_BF16(d, a, b) \
    asm volatile("mma.sync.aligned.m16n8k16.row.col.f32.bf16.bf16.f32 " \
                 "{%0,%1,%2,%3}, {%4,%5,%6,%7}, {%8,%9}, {%0,%1,%2,%3};" \
                 : "+f"((d)[0]), "+f"((d)[1]), "+f"((d)[2]), "+f"((d)[3]) \
                 : "r"((a)[0]), "r"((a)[1]), "r"((a)[2]), "r"((a)[3]), \
                   "r"((b)[0]), "r"((b)[1]))

// ---------------------------------------------------------------------------
// RoPE table
// ---------------------------------------------------------------------------
__global__ void rope_table_kernel() {
    int idx = blockIdx.x * blockDim.x + threadIdx.x;
    if (idx >= SEQ * 64) return;
    int pos = idx >> 6;
    int d   = idx & 63;
    double theta = pow(10000.0, -(double)(2 * d) / 128.0);
    double ang   = (double)pos * theta;
    g_rope[idx] = make_float2((float)sin(ang), (float)cos(ang));
}

// ---------------------------------------------------------------------------
// fp32 -> bf16 hi/lo split kernels
// ---------------------------------------------------------------------------
__device__ __forceinline__ void split1(float v, unsigned short& h, unsigned short& l) {
    __nv_bfloat16 hb = __float2bfloat16_rn(v);
    h = __bfloat16_as_ushort(hb);
    l = __bfloat16_as_ushort(__float2bfloat16_rn(v - __bfloat162float(hb)));
}

__global__ void split_kernel(const float* __restrict__ src,
                             __nv_bfloat16* __restrict__ hi,
                             __nv_bfloat16* __restrict__ lo, int n4) {
    int i = blockIdx.x * blockDim.x + threadIdx.x;
    if (i >= n4) return;
    float4 v = ((const float4*)src)[i];
    ushort4 h, l;
    split1(v.x, h.x, l.x); split1(v.y, h.y, l.y);
    split1(v.z, h.z, l.z); split1(v.w, h.w, l.w);
    ((ushort4*)hi)[i] = h;
    ((ushort4*)lo)[i] = l;
}

__global__ void gather_split_kernel(const float* __restrict__ X) {
    int i = blockIdx.x * blockDim.x + threadIdx.x;
    if (i >= MKV * HID / 4) return;
    int row = i >> 9;
    int c4  = i & 511;
    ushort4 h = {0, 0, 0, 0}, l = {0, 0, 0, 0};
    if (row < NKEY) {
        int srow = (row < NSTART) ? row : row + KOFF;
        float4 v = ((const float4*)X)[(size_t)srow * 512 + c4];
        split1(v.x, h.x, l.x); split1(v.y, h.y, l.y);
        split1(v.z, h.z, l.z); split1(v.w, h.w, l.w);
    }
    ((ushort4*)g_Xghi)[i] = h;
    ((ushort4*)g_Xglo)[i] = l;
}

// ---------------------------------------------------------------------------
// mma.sync bf16 split-K GEMM:
//   C[m,n] = sum_k A(m,k)*B(n,k), fp32 emulated as hi/lo bf16, K_eff = 3*HID.
//   seg0 = Ahi*Bhi, seg1 = Alo*Bhi, seg2 = Ahi*Blo.
// Tile: 128x128, BK=64 bf16, 8 warps (4m x 2n), warp tile 32x64.
// Smem rows padded to 144B -> ldmatrix conflict-free. cp.async double buffer.
// ---------------------------------------------------------------------------
#define GBM 128
#define GBN 128
#define GBK 64
#define GNCHUNK 96              // 6144 / 64
#define SROW 144                // 64 bf16 = 128B data + 16B pad
#define STILE (128 * SROW)      // 18432 B per tile
#define GEMM_SMEM (4 * STILE)   // A0,B0,A1,B1 = 73728 B

template<int ROPE, int GPOS>
__global__ void __launch_bounds__(256)
gemm_bf16(const __nv_bfloat16* __restrict__ Ahi, const __nv_bfloat16* __restrict__ Alo,
          const __nv_bfloat16* __restrict__ Bhi, const __nv_bfloat16* __restrict__ Blo,
          const float* __restrict__ bias, float* __restrict__ C, int Mvalid)
{
    extern __shared__ char smem[];
    const uint32_t sbase = smem_u32(smem);
    const int tid  = threadIdx.x;
    const int wid  = tid >> 5;
    const int lane = tid & 31;
    const int wm   = wid >> 1;       // 0..3 -> rows wm*32
    const int wn   = wid & 1;        // 0..1 -> cols wn*64

    const uint32_t sA[2] = {sbase,             sbase + 2 * STILE};
    const uint32_t sB[2] = {sbase + STILE,     sbase + 3 * STILE};

    const size_t arow0 = (size_t)blockIdx.y * GBM * HID;
    const size_t brow0 = (size_t)blockIdx.x * GBN * HID;

    // loader: 256 threads x 4 chunks of 16B for A, same for B
    const int lrow = tid >> 1;                 // reused pattern: idx = tid + 256*i
    (void)lrow;

    auto load_chunk = [&](int c, int buf) {
        const int seg = c >> 5;
        const int k0  = (c & 31) * GBK;
        const __nv_bfloat16* As = ((seg == 1) ? Alo : Ahi) + arow0 + k0;
        const __nv_bfloat16* Bs = ((seg == 2) ? Blo : Bhi) + brow0 + k0;
#pragma unroll
        for (int i = 0; i < 4; i++) {
            int idx = tid + 256 * i;           // 0..1023
            int row = idx >> 3, c16 = idx & 7;
            CP_ASYNC16(sA[buf] + row * SROW + c16 * 16,
                       (const char*)(As + (size_t)row * HID + c16 * 8));
        }
#pragma unroll
        for (int i = 0; i < 4; i++) {
            int idx = tid + 256 * i;
            int row = idx >> 3, c16 = idx & 7;
            CP_ASYNC16(sB[buf] + row * SROW + c16 * 16,
                       (const char*)(Bs + (size_t)row * HID + c16 * 8));
        }
        CP_COMMIT();
    };

    float acc[2][8][4];
#pragma unroll
    for (int mt = 0; mt < 2; mt++)
#pragma unroll
        for (int nt = 0; nt < 8; nt++)
#pragma unroll
            for (int r = 0; r < 4; r++) acc[mt][nt][r] = 0.f;

    // ldmatrix lane address offsets (within tile, bytes)
    // A m16 tile: lanes 0-15 -> rows 0-15 (k0), lanes 16-31 -> same rows +16B
    const uint32_t a_off = (uint32_t)((lane & 15) * SROW + (lane >> 4) * 16);
    // B n16 group: lanes 0-7 n0-7 k0 | 8-15 n0-7 +16B | 16-23 n8-15 k0 | 24-31 n8-15 +16B
    const uint32_t b_off = (uint32_t)(((lane & 7) + ((lane >> 4) << 3)) * SROW +
                                      ((lane >> 3) & 1) * 16);

    load_chunk(0, 0);

    for (int c = 0; c < GNCHUNK; c++) {
        const int cur = c & 1;
        if (c + 1 < GNCHUNK) {
            load_chunk(c + 1, cur ^ 1);
            CP_WAIT(1);
        } else {
            CP_WAIT(0);
        }
        __syncthreads();

        const uint32_t abase = sA[cur] + wm * 32 * SROW + a_off;
        const uint32_t bbase = sB[cur] + wn * 64 * SROW + b_off;

#pragma unroll
        for (int ks = 0; ks < 4; ks++) {       // 4 k16 steps per 64-chunk
            uint32_t af[2][4];
#pragma unroll
            for (int mt = 0; mt < 2; mt++)
                LDMATRIX_X4(af[mt][0], af[mt][1], af[mt][2], af[mt][3],
                            abase + mt * 16 * SROW + ks * 32);
            uint32_t bf[8][2];
#pragma unroll
            for (int g = 0; g < 4; g++) {
                uint32_t r0, r1, r2, r3;
                LDMATRIX_X4(r0, r1, r2, r3, bbase + g * 16 * SROW + ks * 32);
                bf[g * 2 + 0][0] = r0; bf[g * 2 + 0][1] = r1;
                bf[g * 2 + 1][0] = r2; bf[g * 2 + 1][1] = r3;
            }
#pragma unroll
            for (int mt = 0; mt < 2; mt++)
#pragma unroll
                for (int nt = 0; nt < 8; nt++)
                    MMA_BF16(acc[mt][nt], af[mt], bf[nt]);
        }
        __syncthreads();
    }

    // ---- epilogue: bias (+rope) -> fp32 global ----
#pragma unroll
    for (int mt = 0; mt < 2; mt++) {
        const int rbase = blockIdx.y * GBM + wm * 32 + mt * 16 + (lane >> 2);
#pragma unroll
        for (int half = 0; half < 2; half++) {
            const int r = rbase + half * 8;
            if (r >= Mvalid) continue;
            int pos = r;
            if (GPOS) pos = (r < NSTART) ? r : r + KOFF;
#pragma unroll
            for (int nt = 0; nt < 8; nt++) {
                const int col = blockIdx.x * GBN + wn * 64 + nt * 8 + 2 * (lane & 3);
                float v0 = acc[mt][nt][half * 2 + 0] + __ldg(&bias[col]);
                float v1 = acc[mt][nt][half * 2 + 1] + __ldg(&bias[col + 1]);
                if (ROPE) {
                    const int d = (col & 127) >> 1;
                    float2 sc = g_rope[pos * 64 + d];
                    float x1 = v0, x2 = v1;
                    v0 = x1 * sc.y - x2 * sc.x;
                    v1 = x1 * sc.x + x2 * sc.y;
                }
                *(float2*)(C + (size_t)r * HID + col) = make_float2(v0, v1);
            }
        }
    }
}

// ---------------------------------------------------------------------------
// Flash-style attention over the fixed 1434-key set (FFMA, fp32)
// ---------------------------------------------------------------------------
#define QS_STR 132
#define KS_STR 132
#define VS_STR 128
#define PS_STR 68
#define ATTN_SMEM ((64*QS_STR + 64*KS_STR + 64*VS_STR + 64*PS_STR) * 4)

__global__ void __launch_bounds__(256, 1)
attn_kernel()
{
    extern __shared__ float smf[];
    float* Qs = smf;
    float* Ks = Qs + 64 * QS_STR;
    float* Vs = Ks + 64 * KS_STR;
    float* Ps = Vs + 64 * VS_STR;

    const int qb  = blockIdx.x;
    const int h   = blockIdx.y;
    const int tid = threadIdx.x;
    const int ty  = tid >> 4;
    const int tx  = tid & 15;

    {
        const int row = tid >> 2;
        const int c0  = (tid & 3) * 32;
        const float* src = g_Q + (size_t)(qb * 64 + row) * HID + h * HDIM + c0;
        float* dst = Qs + row * QS_STR + c0;
#pragma unroll
        for (int i = 0; i < 8; i++)
            *(float4*)(dst + 4 * i) = *(const float4*)(src + 4 * i);
    }

    float m[4], l[4], o[4][8];
#pragma unroll
    for (int i = 0; i < 4; i++) {
        m[i] = -INFINITY; l[i] = 0.f;
#pragma unroll
        for (int c = 0; c < 8; c++) o[i][c] = 0.f;
    }

    const float scale = 0.088388347648318447f;
    const int ntiles = (NKEY + 63) >> 6;

    for (int kt = 0; kt < ntiles; kt++) {
        __syncthreads();
        {
            const int row = tid >> 2;
            const int c0  = (tid & 3) * 32;
            const int kr  = kt * 64 + row;
            float* kd = Ks + row * KS_STR + c0;
            float* vd = Vs + row * VS_STR + c0;
            if (kr < NKEY) {
                const float* ks = g_K + (size_t)kr * HID + h * HDIM + c0;
                const float* vs = g_V + (size_t)kr * HID + h * HDIM + c0;
#pragma unroll
                for (int i = 0; i < 8; i++) {
                    *(float4*)(kd + 4 * i) = *(const float4*)(ks + 4 * i);
                    *(float4*)(vd + 4 * i) = *(const float4*)(vs + 4 * i);
                }
            } else {
                float4 z = make_float4(0.f, 0.f, 0.f, 0.f);
#pragma unroll
                for (int i = 0; i < 8; i++) {
                    *(float4*)(kd + 4 * i) = z;
                    *(float4*)(vd + 4 * i) = z;
                }
            }
        }
        __syncthreads();

        float s[4][4];
#pragma unroll
        for (int i = 0; i < 4; i++)
#pragma unroll
            for (int j = 0; j < 4; j++) s[i][j] = 0.f;

        for (int k4 = 0; k4 < 32; k4++) {
            float4 qv[4], kv[4];
#pragma unroll
            for (int i = 0; i < 4; i++)
                qv[i] = *(const float4*)&Qs[(ty * 4 + i) * QS_STR + k4 * 4];
#pragma unroll
            for (int j = 0; j < 4; j++)
                kv[j] = *(const float4*)&Ks[(j * 16 + tx) * KS_STR + k4 * 4];
#pragma unroll
            for (int i = 0; i < 4; i++)
#pragma unroll
                for (int j = 0; j < 4; j++) {
                    s[i][j] = fmaf(qv[i].x, kv[j].x, s[i][j]);
                    s[i][j] = fmaf(qv[i].y, kv[j].y, s[i][j]);
                    s[i][j] = fmaf(qv[i].z, kv[j].z, s[i][j]);
                    s[i][j] = fmaf(qv[i].w, kv[j].w, s[i][j]);
                }
        }

#pragma unroll
        for (int i = 0; i < 4; i++)
#pragma unroll
            for (int j = 0; j < 4; j++) {
                const int kr = kt * 64 + j * 16 + tx;
                s[i][j] = (kr < NKEY) ? s[i][j] * scale : -INFINITY;
            }

#pragma unroll
        for (int i = 0; i < 4; i++) {
            float tmax = fmaxf(fmaxf(s[i][0], s[i][1]), fmaxf(s[i][2], s[i][3]));
#pragma unroll
            for (int w = 8; w >= 1; w >>= 1)
                tmax = fmaxf(tmax, __shfl_xor_sync(0xffffffffu, tmax, w));
            const float mn   = fmaxf(m[i], tmax);
            const float corr = __expf(m[i] - mn);
            float p[4], psum = 0.f;
#pragma unroll
            for (int j = 0; j < 4; j++) {
                p[j] = __expf(s[i][j] - mn);
                psum += p[j];
            }
#pragma unroll
            for (int w = 8; w >= 1; w >>= 1)
                psum += __shfl_xor_sync(0xffffffffu, psum, w);
            l[i] = l[i] * corr + psum;
            m[i] = mn;
#pragma unroll
            for (int c = 0; c < 8; c++) o[i][c] *= corr;
#pragma unroll
            for (int j = 0; j < 4; j++)
                Ps[(j * 16 + tx) * PS_STR + ty * 4 + i] = p[j];
        }
        __syncthreads();

        for (int j = 0; j < 64; j++) {
            float4 pv = *(const float4*)&Ps[j * PS_STR + ty * 4];
            float4 v0 = *(const float4*)&Vs[j * VS_STR + tx * 8];
            float4 v1 = *(const float4*)&Vs[j * VS_STR + tx * 8 + 4];
            float pa[4] = {pv.x, pv.y, pv.z, pv.w};
#pragma unroll
            for (int i = 0; i < 4; i++) {
                o[i][0] = fmaf(pa[i], v0.x, o[i][0]);
                o[i][1] = fmaf(pa[i], v0.y, o[i][1]);
                o[i][2] = fmaf(pa[i], v0.z, o[i][2]);
                o[i][3] = fmaf(pa[i], v0.w, o[i][3]);
                o[i][4] = fmaf(pa[i], v1.x, o[i][4]);
                o[i][5] = fmaf(pa[i], v1.y, o[i][5]);
                o[i][6] = fmaf(pa[i], v1.z, o[i][6]);
                o[i][7] = fmaf(pa[i], v1.w, o[i][7]);
            }
        }
    }

#pragma unroll
    for (int i = 0; i < 4; i++) {
        const float inv = 1.f / l[i];
        float4 r0, r1;
        r0.x = o[i][0] * inv; r0.y = o[i][1] * inv;
        r0.z = o[i][2] * inv; r0.w = o[i][3] * inv;
        r1.x = o[i][4] * inv; r1.y = o[i][5] * inv;
        r1.z = o[i][6] * inv; r1.w = o[i][7] * inv;
        float* dst = g_CTX + (size_t)(qb * 64 + ty * 4 + i) * HID + h * HDIM + tx * 8;
        *(float4*)dst       = r0;
        *(float4*)(dst + 4) = r1;
    }
}

// ---------------------------------------------------------------------------
extern "C" void kernel_launch(void* const* d_in, const int* in_sizes, int n_in,
                              void* d_out, int out_size)
{
    const float* X  = (const float*)d_in[0];
    const float* Wq = (const float*)d_in[1];
    const float* bq = (const float*)d_in[2];
    const float* Wk = (const float*)d_in[3];
    const float* bk = (const float*)d_in[4];
    const float* Wv = (const float*)d_in[5];
    const float* bv = (const float*)d_in[6];
    const float* Wo = (const float*)d_in[7];
    const float* bo = (const float*)d_in[8];
    float* out = (float*)d_out;

    float *Qp, *Kp, *Vp, *Cp;
    __nv_bfloat16 *Xhi, *Xlo, *Xghi_p, *Xglo_p;
    __nv_bfloat16 *Wqh, *Wql, *Wkh, *Wkl, *Wvh, *Wvl, *Woh, *Wol, *Chi, *Clo;
    cudaGetSymbolAddress((void**)&Qp, g_Q);
    cudaGetSymbolAddress((void**)&Kp, g_K);
    cudaGetSymbolAddress((void**)&Vp, g_V);
    cudaGetSymbolAddress((void**)&Cp, g_CTX);
    cudaGetSymbolAddress((void**)&Xhi, g_Xhi);
    cudaGetSymbolAddress((void**)&Xlo, g_Xlo);
    cudaGetSymbolAddress((void**)&Xghi_p, g_Xghi);
    cudaGetSymbolAddress((void**)&Xglo_p, g_Xglo);
    cudaGetSymbolAddress((void**)&Wqh, g_Wqhi);
    cudaGetSymbolAddress((void**)&Wql, g_Wqlo);
    cudaGetSymbolAddress((void**)&Wkh, g_Wkhi);
    cudaGetSymbolAddress((void**)&Wkl, g_Wklo);
    cudaGetSymbolAddress((void**)&Wvh, g_Wvhi);
    cudaGetSymbolAddress((void**)&Wvl, g_Wvlo);
    cudaGetSymbolAddress((void**)&Woh, g_Wohi);
    cudaGetSymbolAddress((void**)&Wol, g_Wolo);
    cudaGetSymbolAddress((void**)&Chi, g_Chi);
    cudaGetSymbolAddress((void**)&Clo, g_Clo);

    cudaFuncSetAttribute(gemm_bf16<1, 0>, cudaFuncAttributeMaxDynamicSharedMemorySize, GEMM_SMEM);
    cudaFuncSetAttribute(gemm_bf16<1, 1>, cudaFuncAttributeMaxDynamicSharedMemorySize, GEMM_SMEM);
    cudaFuncSetAttribute(gemm_bf16<0, 0>, cudaFuncAttributeMaxDynamicSharedMemorySize, GEMM_SMEM);
    cudaFuncSetAttribute(attn_kernel, cudaFuncAttributeMaxDynamicSharedMemorySize, ATTN_SMEM);

    dim3 blk(256);

    rope_table_kernel<<<(SEQ * 64 + 255) / 256, 256>>>();

    split_kernel<<<(SEQ * HID / 4 + 255) / 256, 256>>>(X, Xhi, Xlo, SEQ * HID / 4);
    gather_split_kernel<<<(MKV * HID / 4 + 255) / 256, 256>>>(X);
    split_kernel<<<(HID * HID / 4 + 255) / 256, 256>>>(Wq, Wqh, Wql, HID * HID / 4);
    split_kernel<<<(HID * HID / 4 + 255) / 256, 256>>>(Wk, Wkh, Wkl, HID * HID / 4);
    split_kernel<<<(HID * HID / 4 + 255) / 256, 256>>>(Wv, Wvh, Wvl, HID * HID / 4);
    split_kernel<<<(HID * HID / 4 + 255) / 256, 256>>>(Wo, Woh, Wol, HID * HID / 4);

    // Q = X Wq^T + bq (rope)
    gemm_bf16<1, 0><<<dim3(HID / GBN, SEQ / GBM), blk, GEMM_SMEM>>>(
        Xhi, Xlo, Wqh, Wql, bq, Qp, SEQ);
    // K = Xg Wk^T + bk (rope at gathered positions)
    gemm_bf16<1, 1><<<dim3(HID / GBN, MKV / GBM), blk, GEMM_SMEM>>>(
        Xghi_p, Xglo_p, Wkh, Wkl, bk, Kp, NKEY);
    // V = Xg Wv^T + bv
    gemm_bf16<0, 0><<<dim3(HID / GBN, MKV / GBM), blk, GEMM_SMEM>>>(
        Xghi_p, Xglo_p, Wvh, Wvl, bv, Vp, NKEY);

    attn_kernel<<<dim3(SEQ / 64, NHEAD), blk, ATTN_SMEM>>>();

    split_kernel<<<(SEQ * HID / 4 + 255) / 256, 256>>>(Cp, Chi, Clo, SEQ * HID / 4);

    // out = CTX Wo^T + bo
    gemm_bf16<0, 0><<<dim3(HID / GBN, SEQ / GBM), blk, GEMM_SMEM>>>(
        Chi, Clo, Woh, Wol, bo, out, SEQ);
}